// round 2
// baseline (speedup 1.0000x reference)
#include <cuda_runtime.h>

// Problem constants
#define BB 4
#define SS 2048
#define DD 1024
#define HH 16
#define DK 64
#define M_TOT (BB*SS)   // 8192

// Scratch (device globals: allocation-free per harness rules)
__device__ float g_q[(size_t)BB*HH*SS*DK];   // 32 MB, [B,H,S,64]
__device__ float g_k[(size_t)BB*HH*SS*DK];
__device__ float g_v[(size_t)BB*HH*SS*DK];
__device__ float g_o[(size_t)BB*SS*DD];      // 32 MB, [B,S,D]

// ---------------------------------------------------------------------------
// GEMM: C = A[M,K] @ W[N,K]^T + bias[N]
//   mode 0: C row-major [M, D]  (final output projection)
//   mode 1: write head-split layout [B, H, S, 64] (fused transpose)
// Tile 64x64, BK=16, 256 threads, 4x4 per thread, fp32.
// ---------------------------------------------------------------------------
__global__ __launch_bounds__(256) void gemm_bias_kernel(
    const float* __restrict__ A, const float* __restrict__ W,
    const float* __restrict__ bias, float* __restrict__ Cout, int mode)
{
    const int Kdim = DD;
    __shared__ float As[16][68];   // [k][m], +4 pad keeps float4 alignment
    __shared__ float Bs[16][68];   // [k][n]

    int t  = threadIdx.x;
    int tx = t & 15, ty = t >> 4;
    int bm = blockIdx.y * 64, bn = blockIdx.x * 64;

    // cooperative loads: 256 threads x float4 = 64 rows x 16 cols
    int lr = t >> 2;             // 0..63
    int lc = (t & 3) << 2;       // 0,4,8,12
    const float* Ap = A + (size_t)(bm + lr) * Kdim + lc;
    const float* Wp = W + (size_t)(bn + lr) * Kdim + lc;

    float acc[4][4] = {};

    for (int k0 = 0; k0 < Kdim; k0 += 16) {
        float4 av = *(const float4*)(Ap + k0);
        float4 wv = *(const float4*)(Wp + k0);
        As[lc+0][lr] = av.x; As[lc+1][lr] = av.y;
        As[lc+2][lr] = av.z; As[lc+3][lr] = av.w;
        Bs[lc+0][lr] = wv.x; Bs[lc+1][lr] = wv.y;
        Bs[lc+2][lr] = wv.z; Bs[lc+3][lr] = wv.w;
        __syncthreads();

        #pragma unroll
        for (int kk = 0; kk < 16; kk++) {
            float4 a4 = *(const float4*)&As[kk][ty * 4];
            float4 b4 = *(const float4*)&Bs[kk][tx * 4];
            float a[4] = {a4.x, a4.y, a4.z, a4.w};
            float b[4] = {b4.x, b4.y, b4.z, b4.w};
            #pragma unroll
            for (int i = 0; i < 4; i++)
                #pragma unroll
                for (int j = 0; j < 4; j++)
                    acc[i][j] += a[i] * b[j];
        }
        __syncthreads();
    }

    #pragma unroll
    for (int i = 0; i < 4; i++) {
        int m = bm + ty * 4 + i;
        #pragma unroll
        for (int j = 0; j < 4; j++) {
            int n = bn + tx * 4 + j;
            float v = acc[i][j] + bias[n];
            if (mode == 0) {
                Cout[(size_t)m * DD + n] = v;
            } else {
                int b_ = m >> 11;           // m / 2048
                int s_ = m & 2047;
                int h_ = n >> 6;            // n / 64
                int d_ = n & 63;
                Cout[((((size_t)b_ * HH + h_) * SS + s_) << 6) + d_] = v;
            }
        }
    }
}

// ---------------------------------------------------------------------------
// Flash attention (fp32, online softmax).
// Grid: (S/128, H, B). Block: 128 threads; each thread owns one query row.
// q/o/s register-resident, K/V tiles (32 x 64) staged through smem.
// ---------------------------------------------------------------------------
__global__ __launch_bounds__(128) void flash_kernel()
{
    int t  = threadIdx.x;
    int qb = blockIdx.x, h = blockIdx.y, b = blockIdx.z;

    size_t head_base = ((size_t)b * HH + h) * SS * DK;
    const float* qp = g_q + head_base + (size_t)(qb * 128 + t) * DK;

    __shared__ float Ks[32][64];
    __shared__ float Vs[32][64];

    float q[64], o[64];
    #pragma unroll
    for (int i = 0; i < 16; i++) {
        float4 v = *(const float4*)(qp + i * 4);
        q[4*i+0] = v.x * 0.125f;   // fold 1/sqrt(64) into q
        q[4*i+1] = v.y * 0.125f;
        q[4*i+2] = v.z * 0.125f;
        q[4*i+3] = v.w * 0.125f;
    }
    #pragma unroll
    for (int d = 0; d < 64; d++) o[d] = 0.f;

    float mrun = -1e30f, lrun = 0.f;

    for (int kb = 0; kb < SS / 32; kb++) {
        const float* kp = g_k + head_base + (size_t)kb * 32 * DK;
        const float* vp = g_v + head_base + (size_t)kb * 32 * DK;

        __syncthreads();   // protect previous iteration's tile reads
        #pragma unroll
        for (int i = 0; i < 4; i++) {
            int idx = t + i * 128;          // 0..511
            int r = idx >> 4, c = (idx & 15) << 2;
            *(float4*)&Ks[r][c] = *(const float4*)(kp + r * 64 + c);
            *(float4*)&Vs[r][c] = *(const float4*)(vp + r * 64 + c);
        }
        __syncthreads();

        // scores: s[j] = (q/8) . K[j]
        float s[32];
        #pragma unroll
        for (int j = 0; j < 32; j++) s[j] = 0.f;
        #pragma unroll
        for (int d4 = 0; d4 < 16; d4++) {
            float qx = q[d4*4+0], qy = q[d4*4+1];
            float qz = q[d4*4+2], qw = q[d4*4+3];
            #pragma unroll
            for (int j = 0; j < 32; j++) {
                float4 kv = *(const float4*)&Ks[j][d4 * 4];  // broadcast LDS
                s[j] += qx*kv.x + qy*kv.y + qz*kv.z + qw*kv.w;
            }
        }

        // online softmax update
        float mn = mrun;
        #pragma unroll
        for (int j = 0; j < 32; j++) mn = fmaxf(mn, s[j]);
        float corr = __expf(mrun - mn);
        float psum = 0.f;
        #pragma unroll
        for (int j = 0; j < 32; j++) { s[j] = __expf(s[j] - mn); psum += s[j]; }
        lrun = lrun * corr + psum;
        mrun = mn;

        #pragma unroll
        for (int d = 0; d < 64; d++) o[d] *= corr;

        // o += P @ V
        #pragma unroll
        for (int j = 0; j < 32; j++) {
            float p = s[j];
            #pragma unroll
            for (int d4 = 0; d4 < 16; d4++) {
                float4 vv = *(const float4*)&Vs[j][d4 * 4];  // broadcast LDS
                o[d4*4+0] += p * vv.x;
                o[d4*4+1] += p * vv.y;
                o[d4*4+2] += p * vv.z;
                o[d4*4+3] += p * vv.w;
            }
        }
    }

    float inv = 1.f / lrun;
    // write back to [B, S, D] layout (fused inverse head transpose)
    float* op = g_o + (size_t)(b * SS + qb * 128 + t) * DD + h * DK;
    #pragma unroll
    for (int d4 = 0; d4 < 16; d4++) {
        float4 v;
        v.x = o[d4*4+0] * inv; v.y = o[d4*4+1] * inv;
        v.z = o[d4*4+2] * inv; v.w = o[d4*4+3] * inv;
        *(float4*)(op + d4 * 4) = v;
    }
}

// ---------------------------------------------------------------------------
extern "C" void kernel_launch(void* const* d_in, const int* in_sizes, int n_in,
                              void* d_out, int out_size)
{
    const float* query = (const float*)d_in[0];
    const float* key   = (const float*)d_in[1];
    const float* value = (const float*)d_in[2];
    const float* Wq    = (const float*)d_in[3];
    const float* bq    = (const float*)d_in[4];
    const float* Wk    = (const float*)d_in[5];
    const float* bk    = (const float*)d_in[6];
    const float* Wv    = (const float*)d_in[7];
    const float* bv    = (const float*)d_in[8];
    const float* Wo    = (const float*)d_in[9];
    const float* bo    = (const float*)d_in[10];
    float* out = (float*)d_out;

    float *q_ptr, *k_ptr, *v_ptr, *o_ptr;
    cudaGetSymbolAddress((void**)&q_ptr, g_q);
    cudaGetSymbolAddress((void**)&k_ptr, g_k);
    cudaGetSymbolAddress((void**)&v_ptr, g_v);
    cudaGetSymbolAddress((void**)&o_ptr, g_o);

    dim3 gemm_grid(DD / 64, M_TOT / 64);   // (16, 128)

    gemm_bias_kernel<<<gemm_grid, 256>>>(query, Wq, bq, q_ptr, 1);
    gemm_bias_kernel<<<gemm_grid, 256>>>(key,   Wk, bk, k_ptr, 1);
    gemm_bias_kernel<<<gemm_grid, 256>>>(value, Wv, bv, v_ptr, 1);

    flash_kernel<<<dim3(SS / 128, HH, BB), 128>>>();

    gemm_bias_kernel<<<gemm_grid, 256>>>(o_ptr, Wo, bo, out, 0);
}

// round 6
// speedup vs baseline: 1.3434x; 1.3434x over previous
#include <cuda_runtime.h>
#include <cuda_bf16.h>
#include <cstdint>

// Problem constants
#define BB 4
#define SS 2048
#define DD 1024
#define HH 16
#define DK 64
#define M_TOT (BB*SS)   // 8192

// Scratch (device globals: allocation-free per harness rules)
__device__ float g_q[(size_t)BB*HH*SS*DK];   // 32 MB, [B,H,S,64]
__device__ float g_k[(size_t)BB*HH*SS*DK];
__device__ float g_v[(size_t)BB*HH*SS*DK];
__device__ float g_o[(size_t)BB*SS*DD];      // 32 MB, [B,S,D]

__device__ __forceinline__ uint32_t smem_to_u32(const void* p) {
    uint32_t a;
    asm("{ .reg .u64 t; cvta.to.shared.u64 t, %1; cvt.u32.u64 %0, t; }"
        : "=r"(a) : "l"(p));
    return a;
}

// ldmatrix x4 (non-transposed, b16)
__device__ __forceinline__ void ldm_x4(uint32_t* r, uint32_t addr) {
    asm volatile("ldmatrix.sync.aligned.m8n8.x4.shared.b16 {%0,%1,%2,%3}, [%4];"
                 : "=r"(r[0]), "=r"(r[1]), "=r"(r[2]), "=r"(r[3]) : "r"(addr));
}

// mma.sync m16n8k16 bf16 -> f32
__device__ __forceinline__ void mma16816(float* c, const uint32_t* a, const uint32_t* b) {
    asm volatile(
        "mma.sync.aligned.m16n8k16.row.col.f32.bf16.bf16.f32 "
        "{%0,%1,%2,%3}, {%4,%5,%6,%7}, {%8,%9}, {%0,%1,%2,%3};"
        : "+f"(c[0]), "+f"(c[1]), "+f"(c[2]), "+f"(c[3])
        : "r"(a[0]), "r"(a[1]), "r"(a[2]), "r"(a[3]), "r"(b[0]), "r"(b[1]));
}

// fp32 -> bf16 hi + bf16 lo (residual) for a float4; packed as 2x uint32 each
__device__ __forceinline__ void split4(float4 v, uint2* hi, uint2* lo) {
    __nv_bfloat162 h01 = __floats2bfloat162_rn(v.x, v.y);
    __nv_bfloat162 h23 = __floats2bfloat162_rn(v.z, v.w);
    float l0 = v.x - __bfloat162float(h01.x);
    float l1 = v.y - __bfloat162float(h01.y);
    float l2 = v.z - __bfloat162float(h23.x);
    float l3 = v.w - __bfloat162float(h23.y);
    __nv_bfloat162 L01 = __floats2bfloat162_rn(l0, l1);
    __nv_bfloat162 L23 = __floats2bfloat162_rn(l2, l3);
    hi->x = *(uint32_t*)&h01; hi->y = *(uint32_t*)&h23;
    lo->x = *(uint32_t*)&L01; lo->y = *(uint32_t*)&L23;
}

// ===========================================================================
// GEMM:  C[M_TOT, DD] = A[M_TOT, DD] @ W[DD, DD]^T + bias
// mma.sync bf16 hi/lo split (3 MMAs per product) -> ~fp32 precision.
// CTA tile 128x128, BK=32, 256 threads (8 warps, 2x4 of 64x32).
//   mode 0: C row-major [M, DD]
//   mode 1: C in head-split layout [B, H, S, 64]
// ===========================================================================
#define RSTRIDE 40   // smem row stride in bf16 elems (80 bytes, ldmatrix conflict-free)

__global__ __launch_bounds__(256, 2) void gemm_mma(
    const float* __restrict__ A, const float* __restrict__ W,
    const float* __restrict__ bias, float* __restrict__ C, int mode)
{
    __shared__ __align__(16) uint16_t sAhi[128 * RSTRIDE];
    __shared__ __align__(16) uint16_t sAlo[128 * RSTRIDE];
    __shared__ __align__(16) uint16_t sBhi[128 * RSTRIDE];
    __shared__ __align__(16) uint16_t sBlo[128 * RSTRIDE];

    const int t    = threadIdx.x;
    const int lane = t & 31;
    const int wid  = t >> 5;
    const int bm   = blockIdx.y * 128;
    const int bn   = blockIdx.x * 128;
    const int warpM = wid >> 2;        // 0..1  -> m offset *64
    const int warpN = wid & 3;         // 0..3  -> n offset *32

    float acc[4][4][4];
    #pragma unroll
    for (int i = 0; i < 4; i++)
        #pragma unroll
        for (int j = 0; j < 4; j++)
            #pragma unroll
            for (int e = 0; e < 4; e++) acc[i][j][e] = 0.f;

    const uint32_t aHiB = smem_to_u32(sAhi);
    const uint32_t aLoB = smem_to_u32(sAlo);
    const uint32_t bHiB = smem_to_u32(sBhi);
    const uint32_t bLoB = smem_to_u32(sBlo);

    // per-lane ldmatrix byte offsets (k-step invariant parts)
    // A tile row: warpM*64 + mt*16 + (lane&15); extra +16B for lanes 16-31 (k 8..15)
    const uint32_t aOffBase =
        (uint32_t)((warpM * 64 + (lane & 15)) * (RSTRIDE * 2)) + ((lane >> 4) * 16);
    // B tile row: warpN*32 + pair*16 + (lane&7) + ((lane>>4)*8); +16B when (lane>>3)&1
    const uint32_t bOffBase =
        (uint32_t)((warpN * 32 + (lane & 7) + ((lane >> 4) << 3)) * (RSTRIDE * 2))
        + (((lane >> 3) & 1) * 16);

    // cooperative load indexing: 4 iters x 256 threads = 1024 float4 = 128x32 fp32
    const int lr  = (t + 0) >> 3;       // row advances every 8 threads
    const int lc4 = t & 7;              // float4 column 0..7
    const uint32_t stByte = (uint32_t)(lr * (RSTRIDE * 2) + lc4 * 8);

    for (int kt = 0; kt < DD / 32; kt++) {
        const int k0 = kt * 32;
        __syncthreads();                 // previous iteration's reads complete
        #pragma unroll
        for (int i = 0; i < 4; i++) {
            const int r = lr + i * 32;
            const uint32_t sb = stByte + (uint32_t)(i * 32 * RSTRIDE * 2);
            uint2 hi, lo;
            float4 av = *(const float4*)(A + (size_t)(bm + r) * DD + k0 + lc4 * 4);
            split4(av, &hi, &lo);
            *(uint2*)((char*)sAhi + sb) = hi;
            *(uint2*)((char*)sAlo + sb) = lo;
            float4 wv = *(const float4*)(W + (size_t)(bn + r) * DD + k0 + lc4 * 4);
            split4(wv, &hi, &lo);
            *(uint2*)((char*)sBhi + sb) = hi;
            *(uint2*)((char*)sBlo + sb) = lo;
        }
        __syncthreads();

        #pragma unroll
        for (int ks = 0; ks < 2; ks++) {
            const uint32_t ko = (uint32_t)(ks * 32);   // +32 bytes per k16 step

            // B fragments: 4 ntiles, {b0,b1} each, hi and lo
            uint32_t bhi[4][2], blo[4][2];
            #pragma unroll
            for (int pair = 0; pair < 2; pair++) {
                uint32_t off = bOffBase + (uint32_t)(pair * 16 * RSTRIDE * 2) + ko;
                uint32_t r4[4];
                ldm_x4(r4, bHiB + off);
                bhi[2*pair+0][0] = r4[0]; bhi[2*pair+0][1] = r4[1];
                bhi[2*pair+1][0] = r4[2]; bhi[2*pair+1][1] = r4[3];
                ldm_x4(r4, bLoB + off);
                blo[2*pair+0][0] = r4[0]; blo[2*pair+0][1] = r4[1];
                blo[2*pair+1][0] = r4[2]; blo[2*pair+1][1] = r4[3];
            }

            #pragma unroll
            for (int mt = 0; mt < 4; mt++) {
                uint32_t off = aOffBase + (uint32_t)(mt * 16 * RSTRIDE * 2) + ko;
                uint32_t ahi[4], alo[4];
                ldm_x4(ahi, aHiB + off);
                ldm_x4(alo, aLoB + off);
                #pragma unroll
                for (int nt = 0; nt < 4; nt++) {
                    mma16816(acc[mt][nt], ahi, bhi[nt]);
                    mma16816(acc[mt][nt], ahi, blo[nt]);
                    mma16816(acc[mt][nt], alo, bhi[nt]);
                }
            }
        }
    }

    // Epilogue: fragment -> global with bias
    const int groupID = lane >> 2;
    const int laneCol = (lane & 3) * 2;
    #pragma unroll
    for (int mt = 0; mt < 4; mt++) {
        #pragma unroll
        for (int nt = 0; nt < 4; nt++) {
            const int n = bn + warpN * 32 + nt * 8 + laneCol;
            const float2 bv = *(const float2*)(bias + n);
            #pragma unroll
            for (int h = 0; h < 2; h++) {
                const int m = bm + warpM * 64 + mt * 16 + groupID + h * 8;
                float2 o;
                o.x = acc[mt][nt][2*h+0] + bv.x;
                o.y = acc[mt][nt][2*h+1] + bv.y;
                float* dst;
                if (mode == 0) {
                    dst = C + (size_t)m * DD + n;
                } else {
                    const int b_ = m >> 11, s_ = m & 2047;
                    const int h_ = n >> 6,  d_ = n & 63;
                    dst = C + ((((size_t)b_ * HH + h_) * SS + s_) << 6) + d_;
                }
                *(float2*)dst = o;
            }
        }
    }
}

// ---------------------------------------------------------------------------
// Flash attention (fp32, online softmax) — unchanged (known-good).
// ---------------------------------------------------------------------------
__global__ __launch_bounds__(128) void flash_kernel()
{
    int t  = threadIdx.x;
    int qb = blockIdx.x, h = blockIdx.y, b = blockIdx.z;

    size_t head_base = ((size_t)b * HH + h) * SS * DK;
    const float* qp = g_q + head_base + (size_t)(qb * 128 + t) * DK;

    __shared__ float Ks[32][64];
    __shared__ float Vs[32][64];

    float q[64], o[64];
    #pragma unroll
    for (int i = 0; i < 16; i++) {
        float4 v = *(const float4*)(qp + i * 4);
        q[4*i+0] = v.x * 0.125f;
        q[4*i+1] = v.y * 0.125f;
        q[4*i+2] = v.z * 0.125f;
        q[4*i+3] = v.w * 0.125f;
    }
    #pragma unroll
    for (int d = 0; d < 64; d++) o[d] = 0.f;

    float mrun = -1e30f, lrun = 0.f;

    for (int kb = 0; kb < SS / 32; kb++) {
        const float* kp = g_k + head_base + (size_t)kb * 32 * DK;
        const float* vp = g_v + head_base + (size_t)kb * 32 * DK;

        __syncthreads();
        #pragma unroll
        for (int i = 0; i < 4; i++) {
            int idx = t + i * 128;
            int r = idx >> 4, cc = (idx & 15) << 2;
            *(float4*)&Ks[r][cc] = *(const float4*)(kp + r * 64 + cc);
            *(float4*)&Vs[r][cc] = *(const float4*)(vp + r * 64 + cc);
        }
        __syncthreads();

        float s[32];
        #pragma unroll
        for (int j = 0; j < 32; j++) s[j] = 0.f;
        #pragma unroll
        for (int d4 = 0; d4 < 16; d4++) {
            float qx = q[d4*4+0], qy = q[d4*4+1];
            float qz = q[d4*4+2], qw = q[d4*4+3];
            #pragma unroll
            for (int j = 0; j < 32; j++) {
                float4 kv = *(const float4*)&Ks[j][d4 * 4];
                s[j] += qx*kv.x + qy*kv.y + qz*kv.z + qw*kv.w;
            }
        }

        float mn = mrun;
        #pragma unroll
        for (int j = 0; j < 32; j++) mn = fmaxf(mn, s[j]);
        float corr = __expf(mrun - mn);
        float psum = 0.f;
        #pragma unroll
        for (int j = 0; j < 32; j++) { s[j] = __expf(s[j] - mn); psum += s[j]; }
        lrun = lrun * corr + psum;
        mrun = mn;

        #pragma unroll
        for (int d = 0; d < 64; d++) o[d] *= corr;

        #pragma unroll
        for (int j = 0; j < 32; j++) {
            float p = s[j];
            #pragma unroll
            for (int d4 = 0; d4 < 16; d4++) {
                float4 vv = *(const float4*)&Vs[j][d4 * 4];
                o[d4*4+0] += p * vv.x;
                o[d4*4+1] += p * vv.y;
                o[d4*4+2] += p * vv.z;
                o[d4*4+3] += p * vv.w;
            }
        }
    }

    float inv = 1.f / lrun;
    float* op = g_o + (size_t)(b * SS + qb * 128 + t) * DD + h * DK;
    #pragma unroll
    for (int d4 = 0; d4 < 16; d4++) {
        float4 v;
        v.x = o[d4*4+0] * inv; v.y = o[d4*4+1] * inv;
        v.z = o[d4*4+2] * inv; v.w = o[d4*4+3] * inv;
        *(float4*)(op + d4 * 4) = v;
    }
}

// ---------------------------------------------------------------------------
extern "C" void kernel_launch(void* const* d_in, const int* in_sizes, int n_in,
                              void* d_out, int out_size)
{
    const float* query = (const float*)d_in[0];
    const float* key   = (const float*)d_in[1];
    const float* value = (const float*)d_in[2];
    const float* Wq    = (const float*)d_in[3];
    const float* bq    = (const float*)d_in[4];
    const float* Wk    = (const float*)d_in[5];
    const float* bk    = (const float*)d_in[6];
    const float* Wv    = (const float*)d_in[7];
    const float* bv    = (const float*)d_in[8];
    const float* Wo    = (const float*)d_in[9];
    const float* bo    = (const float*)d_in[10];
    float* out = (float*)d_out;

    float *q_ptr, *k_ptr, *v_ptr, *o_ptr;
    cudaGetSymbolAddress((void**)&q_ptr, g_q);
    cudaGetSymbolAddress((void**)&k_ptr, g_k);
    cudaGetSymbolAddress((void**)&v_ptr, g_v);
    cudaGetSymbolAddress((void**)&o_ptr, g_o);

    dim3 gemm_grid(DD / 128, M_TOT / 128);   // (8, 64)

    gemm_mma<<<gemm_grid, 256>>>(query, Wq, bq, q_ptr, 1);
    gemm_mma<<<gemm_grid, 256>>>(key,   Wk, bk, k_ptr, 1);
    gemm_mma<<<gemm_grid, 256>>>(value, Wv, bv, v_ptr, 1);

    flash_kernel<<<dim3(SS / 128, HH, BB), 128>>>();

    gemm_mma<<<gemm_grid, 256>>>(o_ptr, Wo, bo, out, 0);
}

// round 7
// speedup vs baseline: 3.7602x; 2.7990x over previous
#include <cuda_runtime.h>
#include <cuda_bf16.h>
#include <cstdint>

// Problem constants
#define BB 4
#define SS 2048
#define DD 1024
#define HH 16
#define DK 64
#define M_TOT (BB*SS)   // 8192

// Scratch (device globals: allocation-free per harness rules)
__device__ float g_q[(size_t)BB*HH*SS*DK];   // 32 MB, [B,H,S,64]
__device__ float g_k[(size_t)BB*HH*SS*DK];
__device__ float g_v[(size_t)BB*HH*SS*DK];
__device__ float g_o[(size_t)BB*SS*DD];      // 32 MB, [B,S,D]

__device__ __forceinline__ uint32_t smem_to_u32(const void* p) {
    uint32_t a;
    asm("{ .reg .u64 t; cvta.to.shared.u64 t, %1; cvt.u32.u64 %0, t; }"
        : "=r"(a) : "l"(p));
    return a;
}

// ldmatrix x4 (non-transposed, b16)
__device__ __forceinline__ void ldm_x4(uint32_t* r, uint32_t addr) {
    asm volatile("ldmatrix.sync.aligned.m8n8.x4.shared.b16 {%0,%1,%2,%3}, [%4];"
                 : "=r"(r[0]), "=r"(r[1]), "=r"(r[2]), "=r"(r[3]) : "r"(addr));
}
// ldmatrix x4 transposed
__device__ __forceinline__ void ldm_x4_t(uint32_t* r, uint32_t addr) {
    asm volatile("ldmatrix.sync.aligned.m8n8.x4.trans.shared.b16 {%0,%1,%2,%3}, [%4];"
                 : "=r"(r[0]), "=r"(r[1]), "=r"(r[2]), "=r"(r[3]) : "r"(addr));
}

// mma.sync m16n8k16 bf16 -> f32
__device__ __forceinline__ void mma16816(float* c, const uint32_t* a, const uint32_t* b) {
    asm volatile(
        "mma.sync.aligned.m16n8k16.row.col.f32.bf16.bf16.f32 "
        "{%0,%1,%2,%3}, {%4,%5,%6,%7}, {%8,%9}, {%0,%1,%2,%3};"
        : "+f"(c[0]), "+f"(c[1]), "+f"(c[2]), "+f"(c[3])
        : "r"(a[0]), "r"(a[1]), "r"(a[2]), "r"(a[3]), "r"(b[0]), "r"(b[1]));
}

// fp32 -> bf16 hi + bf16 lo (residual) for a float4; packed as 2x uint32 each
__device__ __forceinline__ void split4(float4 v, uint2* hi, uint2* lo) {
    __nv_bfloat162 h01 = __floats2bfloat162_rn(v.x, v.y);
    __nv_bfloat162 h23 = __floats2bfloat162_rn(v.z, v.w);
    float l0 = v.x - __bfloat162float(h01.x);
    float l1 = v.y - __bfloat162float(h01.y);
    float l2 = v.z - __bfloat162float(h23.x);
    float l3 = v.w - __bfloat162float(h23.y);
    __nv_bfloat162 L01 = __floats2bfloat162_rn(l0, l1);
    __nv_bfloat162 L23 = __floats2bfloat162_rn(l2, l3);
    hi->x = *(uint32_t*)&h01; hi->y = *(uint32_t*)&h23;
    lo->x = *(uint32_t*)&L01; lo->y = *(uint32_t*)&L23;
}

// split two floats into packed bf16x2 hi and lo
__device__ __forceinline__ void split2(float a, float b, uint32_t* hi, uint32_t* lo) {
    __nv_bfloat162 h = __floats2bfloat162_rn(a, b);
    float la = a - __bfloat162float(h.x);
    float lb = b - __bfloat162float(h.y);
    __nv_bfloat162 L = __floats2bfloat162_rn(la, lb);
    *hi = *(uint32_t*)&h;
    *lo = *(uint32_t*)&L;
}

// ===========================================================================
// GEMM:  C[M_TOT, DD] = A[M_TOT, DD] @ W[DD, DD]^T + bias  (unchanged R5)
// ===========================================================================
#define RSTRIDE 40   // smem row stride in bf16 elems (80 bytes)

__global__ __launch_bounds__(256, 2) void gemm_mma(
    const float* __restrict__ A, const float* __restrict__ W,
    const float* __restrict__ bias, float* __restrict__ C, int mode)
{
    __shared__ __align__(16) uint16_t sAhi[128 * RSTRIDE];
    __shared__ __align__(16) uint16_t sAlo[128 * RSTRIDE];
    __shared__ __align__(16) uint16_t sBhi[128 * RSTRIDE];
    __shared__ __align__(16) uint16_t sBlo[128 * RSTRIDE];

    const int t    = threadIdx.x;
    const int lane = t & 31;
    const int wid  = t >> 5;
    const int bm   = blockIdx.y * 128;
    const int bn   = blockIdx.x * 128;
    const int warpM = wid >> 2;
    const int warpN = wid & 3;

    float acc[4][4][4];
    #pragma unroll
    for (int i = 0; i < 4; i++)
        #pragma unroll
        for (int j = 0; j < 4; j++)
            #pragma unroll
            for (int e = 0; e < 4; e++) acc[i][j][e] = 0.f;

    const uint32_t aHiB = smem_to_u32(sAhi);
    const uint32_t aLoB = smem_to_u32(sAlo);
    const uint32_t bHiB = smem_to_u32(sBhi);
    const uint32_t bLoB = smem_to_u32(sBlo);

    const uint32_t aOffBase =
        (uint32_t)((warpM * 64 + (lane & 15)) * (RSTRIDE * 2)) + ((lane >> 4) * 16);
    const uint32_t bOffBase =
        (uint32_t)((warpN * 32 + (lane & 7) + ((lane >> 4) << 3)) * (RSTRIDE * 2))
        + (((lane >> 3) & 1) * 16);

    const int lr  = t >> 3;
    const int lc4 = t & 7;
    const uint32_t stByte = (uint32_t)(lr * (RSTRIDE * 2) + lc4 * 8);

    for (int kt = 0; kt < DD / 32; kt++) {
        const int k0 = kt * 32;
        __syncthreads();
        #pragma unroll
        for (int i = 0; i < 4; i++) {
            const int r = lr + i * 32;
            const uint32_t sb = stByte + (uint32_t)(i * 32 * RSTRIDE * 2);
            uint2 hi, lo;
            float4 av = *(const float4*)(A + (size_t)(bm + r) * DD + k0 + lc4 * 4);
            split4(av, &hi, &lo);
            *(uint2*)((char*)sAhi + sb) = hi;
            *(uint2*)((char*)sAlo + sb) = lo;
            float4 wv = *(const float4*)(W + (size_t)(bn + r) * DD + k0 + lc4 * 4);
            split4(wv, &hi, &lo);
            *(uint2*)((char*)sBhi + sb) = hi;
            *(uint2*)((char*)sBlo + sb) = lo;
        }
        __syncthreads();

        #pragma unroll
        for (int ks = 0; ks < 2; ks++) {
            const uint32_t ko = (uint32_t)(ks * 32);
            uint32_t bhi[4][2], blo[4][2];
            #pragma unroll
            for (int pair = 0; pair < 2; pair++) {
                uint32_t off = bOffBase + (uint32_t)(pair * 16 * RSTRIDE * 2) + ko;
                uint32_t r4[4];
                ldm_x4(r4, bHiB + off);
                bhi[2*pair+0][0] = r4[0]; bhi[2*pair+0][1] = r4[1];
                bhi[2*pair+1][0] = r4[2]; bhi[2*pair+1][1] = r4[3];
                ldm_x4(r4, bLoB + off);
                blo[2*pair+0][0] = r4[0]; blo[2*pair+0][1] = r4[1];
                blo[2*pair+1][0] = r4[2]; blo[2*pair+1][1] = r4[3];
            }
            #pragma unroll
            for (int mt = 0; mt < 4; mt++) {
                uint32_t off = aOffBase + (uint32_t)(mt * 16 * RSTRIDE * 2) + ko;
                uint32_t ahi[4], alo[4];
                ldm_x4(ahi, aHiB + off);
                ldm_x4(alo, aLoB + off);
                #pragma unroll
                for (int nt = 0; nt < 4; nt++) {
                    mma16816(acc[mt][nt], ahi, bhi[nt]);
                    mma16816(acc[mt][nt], ahi, blo[nt]);
                    mma16816(acc[mt][nt], alo, bhi[nt]);
                }
            }
        }
    }

    const int groupID = lane >> 2;
    const int laneCol = (lane & 3) * 2;
    #pragma unroll
    for (int mt = 0; mt < 4; mt++) {
        #pragma unroll
        for (int nt = 0; nt < 4; nt++) {
            const int n = bn + warpN * 32 + nt * 8 + laneCol;
            const float2 bv = *(const float2*)(bias + n);
            #pragma unroll
            for (int h = 0; h < 2; h++) {
                const int m = bm + warpM * 64 + mt * 16 + groupID + h * 8;
                float2 o;
                o.x = acc[mt][nt][2*h+0] + bv.x;
                o.y = acc[mt][nt][2*h+1] + bv.y;
                float* dst;
                if (mode == 0) {
                    dst = C + (size_t)m * DD + n;
                } else {
                    const int b_ = m >> 11, s_ = m & 2047;
                    const int h_ = n >> 6,  d_ = n & 63;
                    dst = C + ((((size_t)b_ * HH + h_) * SS + s_) << 6) + d_;
                }
                *(float2*)dst = o;
            }
        }
    }
}

// ===========================================================================
// Tensor-core flash attention.
// CTA: one (b,h), 128 q-rows, 4 warps x 32 rows. KV tile = 64 keys.
// QK^T: Q,K bf16 hi/lo (3 MMAs). PV: P,V bf16 hi/lo (3 MMAs).
// smem row stride 144B (conflict-free ldmatrix).
// ===========================================================================
#define FST 144            // bytes per 64-elem bf16 row (64*2 + 16 pad)
#define FQHI 0
#define FQLO 18432
#define FKHI 36864
#define FKLO 46080
#define FVHI 55296
#define FVLO 64512
#define FSM_TOTAL 73728

__global__ __launch_bounds__(128, 2) void flash_mma()
{
    extern __shared__ char fsm[];
    const int t    = threadIdx.x;
    const int lane = t & 31;
    const int warp = t >> 5;
    const int qb = blockIdx.x, h = blockIdx.y, b = blockIdx.z;

    const size_t head_base = ((size_t)b * HH + h) * SS * DK;
    const float* Qg = g_q + head_base + (size_t)qb * 128 * DK;
    const float* Kg = g_k + head_base;
    const float* Vg = g_v + head_base;

    const uint32_t qHiB = smem_to_u32(fsm + FQHI);
    const uint32_t qLoB = smem_to_u32(fsm + FQLO);
    const uint32_t kHiB = smem_to_u32(fsm + FKHI);
    const uint32_t kLoB = smem_to_u32(fsm + FKLO);
    const uint32_t vHiB = smem_to_u32(fsm + FVHI);
    const uint32_t vLoB = smem_to_u32(fsm + FVLO);

    // --- stage Q (scaled by 1/8) as bf16 hi/lo ---
    #pragma unroll
    for (int i = 0; i < 16; i++) {
        int idx = t + i * 128;           // 0..2047
        int r = idx >> 4, c4 = idx & 15;
        float4 v = *(const float4*)(Qg + r * 64 + c4 * 4);
        v.x *= 0.125f; v.y *= 0.125f; v.z *= 0.125f; v.w *= 0.125f;
        uint2 hi, lo; split4(v, &hi, &lo);
        uint32_t byo = (uint32_t)(r * FST + c4 * 8);
        *(uint2*)(fsm + FQHI + byo) = hi;
        *(uint2*)(fsm + FQLO + byo) = lo;
    }

    float o[2][8][4];
    #pragma unroll
    for (int mt = 0; mt < 2; mt++)
        #pragma unroll
        for (int nv = 0; nv < 8; nv++)
            #pragma unroll
            for (int e = 0; e < 4; e++) o[mt][nv][e] = 0.f;
    float mrow[2][2] = {{-1e30f, -1e30f}, {-1e30f, -1e30f}};
    float lrow[2][2] = {{0.f, 0.f}, {0.f, 0.f}};

    // fragment address components
    const uint32_t aRow  = (uint32_t)(warp * 32 + (lane & 15));
    const uint32_t aCol  = (uint32_t)((lane >> 4) << 4);
    const uint32_t kRow  = (uint32_t)((lane & 7) + ((lane >> 4) << 3));
    const uint32_t kCol  = (uint32_t)(((lane >> 3) & 1) << 4);
    const uint32_t vRow  = (uint32_t)(lane & 15);
    const uint32_t vCol  = (uint32_t)((lane >> 4) << 4);

    // conversion indexing: 1024 float4 per tile, 8 per thread
    const int cr  = t >> 4;              // advances 8 rows/iter
    const int cc4 = t & 15;

    for (int kb = 0; kb < SS / 64; kb++) {
        const float* kp = Kg + (size_t)kb * 64 * DK;
        const float* vp = Vg + (size_t)kb * 64 * DK;

        __syncthreads();
        #pragma unroll
        for (int i = 0; i < 8; i++) {
            const int r = cr + i * 8;
            const uint32_t byo = (uint32_t)(r * FST + cc4 * 8);
            uint2 hi, lo;
            float4 kv = *(const float4*)(kp + r * 64 + cc4 * 4);
            split4(kv, &hi, &lo);
            *(uint2*)(fsm + FKHI + byo) = hi;
            *(uint2*)(fsm + FKLO + byo) = lo;
            float4 vv = *(const float4*)(vp + r * 64 + cc4 * 4);
            split4(vv, &hi, &lo);
            *(uint2*)(fsm + FVHI + byo) = hi;
            *(uint2*)(fsm + FVLO + byo) = lo;
        }
        __syncthreads();

        // ---- QK^T: s[2][8][4] ----
        float s[2][8][4];
        #pragma unroll
        for (int mt = 0; mt < 2; mt++)
            #pragma unroll
            for (int nt = 0; nt < 8; nt++)
                #pragma unroll
                for (int e = 0; e < 4; e++) s[mt][nt][e] = 0.f;

        #pragma unroll
        for (int ks = 0; ks < 4; ks++) {
            const uint32_t ko = (uint32_t)(ks * 32);
            uint32_t bhi[8][2], blo[8][2];
            #pragma unroll
            for (int pp = 0; pp < 4; pp++) {
                uint32_t off = (kRow + pp * 16) * FST + kCol + ko;
                uint32_t r4[4];
                ldm_x4(r4, kHiB + off);
                bhi[2*pp+0][0] = r4[0]; bhi[2*pp+0][1] = r4[1];
                bhi[2*pp+1][0] = r4[2]; bhi[2*pp+1][1] = r4[3];
                ldm_x4(r4, kLoB + off);
                blo[2*pp+0][0] = r4[0]; blo[2*pp+0][1] = r4[1];
                blo[2*pp+1][0] = r4[2]; blo[2*pp+1][1] = r4[3];
            }
            #pragma unroll
            for (int mt = 0; mt < 2; mt++) {
                uint32_t off = (aRow + mt * 16) * FST + aCol + ko;
                uint32_t ahi[4], alo[4];
                ldm_x4(ahi, qHiB + off);
                ldm_x4(alo, qLoB + off);
                #pragma unroll
                for (int nt = 0; nt < 8; nt++) {
                    mma16816(s[mt][nt], ahi, bhi[nt]);
                    mma16816(s[mt][nt], ahi, blo[nt]);
                    mma16816(s[mt][nt], alo, bhi[nt]);
                }
            }
        }

        // ---- online softmax ----
        #pragma unroll
        for (int mt = 0; mt < 2; mt++) {
            float mx0 = -1e30f, mx1 = -1e30f;
            #pragma unroll
            for (int nt = 0; nt < 8; nt++) {
                mx0 = fmaxf(mx0, fmaxf(s[mt][nt][0], s[mt][nt][1]));
                mx1 = fmaxf(mx1, fmaxf(s[mt][nt][2], s[mt][nt][3]));
            }
            mx0 = fmaxf(mx0, __shfl_xor_sync(0xffffffffu, mx0, 1));
            mx0 = fmaxf(mx0, __shfl_xor_sync(0xffffffffu, mx0, 2));
            mx1 = fmaxf(mx1, __shfl_xor_sync(0xffffffffu, mx1, 1));
            mx1 = fmaxf(mx1, __shfl_xor_sync(0xffffffffu, mx1, 2));

            const float mn0 = fmaxf(mrow[mt][0], mx0);
            const float mn1 = fmaxf(mrow[mt][1], mx1);
            const float c0 = __expf(mrow[mt][0] - mn0);
            const float c1 = __expf(mrow[mt][1] - mn1);
            mrow[mt][0] = mn0; mrow[mt][1] = mn1;

            float sum0 = 0.f, sum1 = 0.f;
            #pragma unroll
            for (int nt = 0; nt < 8; nt++) {
                float p0 = __expf(s[mt][nt][0] - mn0);
                float p1 = __expf(s[mt][nt][1] - mn0);
                float p2 = __expf(s[mt][nt][2] - mn1);
                float p3 = __expf(s[mt][nt][3] - mn1);
                s[mt][nt][0] = p0; s[mt][nt][1] = p1;
                s[mt][nt][2] = p2; s[mt][nt][3] = p3;
                sum0 += p0 + p1; sum1 += p2 + p3;
            }
            sum0 += __shfl_xor_sync(0xffffffffu, sum0, 1);
            sum0 += __shfl_xor_sync(0xffffffffu, sum0, 2);
            sum1 += __shfl_xor_sync(0xffffffffu, sum1, 1);
            sum1 += __shfl_xor_sync(0xffffffffu, sum1, 2);
            lrow[mt][0] = lrow[mt][0] * c0 + sum0;
            lrow[mt][1] = lrow[mt][1] * c1 + sum1;

            #pragma unroll
            for (int nv = 0; nv < 8; nv++) {
                o[mt][nv][0] *= c0; o[mt][nv][1] *= c0;
                o[mt][nv][2] *= c1; o[mt][nv][3] *= c1;
            }
        }

        // ---- PV ----
        #pragma unroll
        for (int ks = 0; ks < 4; ks++) {
            uint32_t vhi[8][2], vlo[8][2];
            #pragma unroll
            for (int pv = 0; pv < 4; pv++) {
                uint32_t off = (vRow + ks * 16) * FST + pv * 32 + vCol;
                uint32_t r4[4];
                ldm_x4_t(r4, vHiB + off);
                vhi[2*pv+0][0] = r4[0]; vhi[2*pv+0][1] = r4[1];
                vhi[2*pv+1][0] = r4[2]; vhi[2*pv+1][1] = r4[3];
                ldm_x4_t(r4, vLoB + off);
                vlo[2*pv+0][0] = r4[0]; vlo[2*pv+0][1] = r4[1];
                vlo[2*pv+1][0] = r4[2]; vlo[2*pv+1][1] = r4[3];
            }
            #pragma unroll
            for (int mt = 0; mt < 2; mt++) {
                uint32_t phi[4], plo[4];
                split2(s[mt][2*ks+0][0], s[mt][2*ks+0][1], &phi[0], &plo[0]);
                split2(s[mt][2*ks+0][2], s[mt][2*ks+0][3], &phi[1], &plo[1]);
                split2(s[mt][2*ks+1][0], s[mt][2*ks+1][1], &phi[2], &plo[2]);
                split2(s[mt][2*ks+1][2], s[mt][2*ks+1][3], &phi[3], &plo[3]);
                #pragma unroll
                for (int nv = 0; nv < 8; nv++) {
                    mma16816(o[mt][nv], phi, vhi[nv]);
                    mma16816(o[mt][nv], phi, vlo[nv]);
                    mma16816(o[mt][nv], plo, vhi[nv]);
                }
            }
        }
    }

    // ---- epilogue: normalize, write [B,S,D] ----
    const int groupID = lane >> 2;
    const int laneCol = (lane & 3) * 2;
    #pragma unroll
    for (int mt = 0; mt < 2; mt++) {
        const float inv0 = 1.f / lrow[mt][0];
        const float inv1 = 1.f / lrow[mt][1];
        const int r0 = qb * 128 + warp * 32 + mt * 16 + groupID;
        #pragma unroll
        for (int nv = 0; nv < 8; nv++) {
            const int col = h * 64 + nv * 8 + laneCol;
            float2 w0, w1;
            w0.x = o[mt][nv][0] * inv0; w0.y = o[mt][nv][1] * inv0;
            w1.x = o[mt][nv][2] * inv1; w1.y = o[mt][nv][3] * inv1;
            *(float2*)(g_o + (size_t)(b * SS + r0)     * DD + col) = w0;
            *(float2*)(g_o + (size_t)(b * SS + r0 + 8) * DD + col) = w1;
        }
    }
}

// ---------------------------------------------------------------------------
extern "C" void kernel_launch(void* const* d_in, const int* in_sizes, int n_in,
                              void* d_out, int out_size)
{
    const float* query = (const float*)d_in[0];
    const float* key   = (const float*)d_in[1];
    const float* value = (const float*)d_in[2];
    const float* Wq    = (const float*)d_in[3];
    const float* bq    = (const float*)d_in[4];
    const float* Wk    = (const float*)d_in[5];
    const float* bk    = (const float*)d_in[6];
    const float* Wv    = (const float*)d_in[7];
    const float* bv    = (const float*)d_in[8];
    const float* Wo    = (const float*)d_in[9];
    const float* bo    = (const float*)d_in[10];
    float* out = (float*)d_out;

    float *q_ptr, *k_ptr, *v_ptr, *o_ptr;
    cudaGetSymbolAddress((void**)&q_ptr, g_q);
    cudaGetSymbolAddress((void**)&k_ptr, g_k);
    cudaGetSymbolAddress((void**)&v_ptr, g_v);
    cudaGetSymbolAddress((void**)&o_ptr, g_o);

    cudaFuncSetAttribute(flash_mma, cudaFuncAttributeMaxDynamicSharedMemorySize, FSM_TOTAL);

    dim3 gemm_grid(DD / 128, M_TOT / 128);   // (8, 64)

    gemm_mma<<<gemm_grid, 256>>>(query, Wq, bq, q_ptr, 1);
    gemm_mma<<<gemm_grid, 256>>>(key,   Wk, bk, k_ptr, 1);
    gemm_mma<<<gemm_grid, 256>>>(value, Wv, bv, v_ptr, 1);

    flash_mma<<<dim3(SS / 128, HH, BB), 128, FSM_TOTAL>>>();

    gemm_mma<<<gemm_grid, 256>>>(o_ptr, Wo, bo, out, 0);
}